// round 4
// baseline (speedup 1.0000x reference)
#include <cuda_runtime.h>
#include <cuda_bf16.h>
#include <stdint.h>

#define N_NODES 100000
#define N_EDGES 640000
#define HID     128
#define EPS     1e-6f

// Scratch (allocation-free rule: __device__ globals)
__device__ float g_c1[HID];
__device__ float g_c2[HID];
__device__ float g_cconst;
__device__ int   g_is64;
__device__ float g_alpha[N_NODES];
__device__ float g_beta[N_NODES];
__device__ float g_n[N_NODES];

// ---------------------------------------------------------------------------
// Fused prep + dtype detection. 1 block, 512 threads.
// ---------------------------------------------------------------------------
__global__ void k_prep(const float* __restrict__ W,
                       const float* __restrict__ b,
                       const float* __restrict__ att_w,
                       const long long* __restrict__ e64) {
    __shared__ float s1[512];
    __shared__ float s2[512];
    int tid  = threadIdx.x;
    int k    = tid & 127;
    int part = tid >> 7;          // 0..3

    float c1 = 0.f, c2 = 0.f;
    int j0 = part * 32;
    #pragma unroll 8
    for (int j = j0; j < j0 + 32; ++j) {
        float w = W[j * HID + k];
        c1 = fmaf(att_w[j],       w, c1);
        c2 = fmaf(att_w[HID + j], w, c2);
    }
    s1[tid] = c1; s2[tid] = c2;
    __syncthreads();

    if (part == 0) {
        g_c1[k] = s1[k] + s1[k + 128] + s1[k + 256] + s1[k + 384];
        g_c2[k] = s2[k] + s2[k + 128] + s2[k + 256] + s2[k + 384];
    }
    __syncthreads();

    if (tid < 128) s1[tid] = (att_w[tid] + att_w[HID + tid]) * b[tid];
    __syncthreads();

    if (tid == 0) {
        float cc = 0.f;
        #pragma unroll 8
        for (int j = 0; j < HID; ++j) cc += s1[j];
        g_cconst = cc;

        // int64-vs-int32 detection (jax x64-disabled trap)
        bool is64 = true;
        #pragma unroll
        for (int i = 0; i < 8; ++i) {
            long long v = e64[i];
            if (v < 0 || v >= (long long)N_NODES) is64 = false;
        }
        g_is64 = is64 ? 1 : 0;
    }
}

// ---------------------------------------------------------------------------
// Per-node scalars, FOUR nodes per warp (8 lanes per node):
//   sub = lane>>3 selects node, sl = lane&7 owns float4 cols sl, sl+8, sl+16, sl+24.
// (a, beta) packed into one 64-bit shuffle; butterfly {4,2,1}.
// ---------------------------------------------------------------------------
__global__ void k_node(const float* __restrict__ x) {
    int gw   = (blockIdx.x * blockDim.x + threadIdx.x) >> 5;
    int lane = threadIdx.x & 31;
    int sub  = lane >> 3;
    int sl   = lane & 7;
    int node = gw * 4 + sub;
    if (node >= N_NODES) return;

    const float4* xr = reinterpret_cast<const float4*>(x + (size_t)node * HID);
    float4 v0 = __ldg(&xr[sl]);
    float4 v1 = __ldg(&xr[sl + 8]);
    float4 v2 = __ldg(&xr[sl + 16]);
    float4 v3 = __ldg(&xr[sl + 24]);

    const float4* C1 = reinterpret_cast<const float4*>(g_c1);
    const float4* C2 = reinterpret_cast<const float4*>(g_c2);
    float4 p, q;
    float a = 0.f, bt = 0.f;
    p = C1[sl];      q = C2[sl];
    a  += v0.x*p.x + v0.y*p.y + v0.z*p.z + v0.w*p.w;
    bt += v0.x*q.x + v0.y*q.y + v0.z*q.z + v0.w*q.w;
    p = C1[sl + 8];  q = C2[sl + 8];
    a  += v1.x*p.x + v1.y*p.y + v1.z*p.z + v1.w*p.w;
    bt += v1.x*q.x + v1.y*q.y + v1.z*q.z + v1.w*q.w;
    p = C1[sl + 16]; q = C2[sl + 16];
    a  += v2.x*p.x + v2.y*p.y + v2.z*p.z + v2.w*p.w;
    bt += v2.x*q.x + v2.y*q.y + v2.z*q.z + v2.w*q.w;
    p = C1[sl + 24]; q = C2[sl + 24];
    a  += v3.x*p.x + v3.y*p.y + v3.z*p.z + v3.w*p.w;
    bt += v3.x*q.x + v3.y*q.y + v3.z*q.z + v3.w*q.w;

    // packed butterfly within 8-lane groups
    unsigned long long pk = ((unsigned long long)__float_as_uint(bt) << 32)
                          | (unsigned long long)__float_as_uint(a);
    #pragma unroll
    for (int o = 4; o > 0; o >>= 1) {
        unsigned long long other = __shfl_xor_sync(0xFFFFFFFFu, pk, o);
        float oa  = __uint_as_float((unsigned)(other & 0xFFFFFFFFull));
        float obt = __uint_as_float((unsigned)(other >> 32));
        a += oa; bt += obt;
        pk = ((unsigned long long)__float_as_uint(bt) << 32)
           | (unsigned long long)__float_as_uint(a);
    }
    if (sl == 0) {
        g_alpha[node] = a;
        g_beta[node]  = bt;
        g_n[node]     = 0.f;
    }
}

// ---------------------------------------------------------------------------
// Per-edge: n[dst] += exp(leaky_relu(alpha[src] + beta[dst] + cconst)).
// 8 edges/thread. int32 path: int4 = 2 edges per 16B load (4 loads).
// ---------------------------------------------------------------------------
#define EDGE_U 8
#define EDGE_TOT (N_EDGES / EDGE_U)   // 80000 threads

__global__ void k_edges(const void* __restrict__ e_raw) {
    int t = blockIdx.x * blockDim.x + threadIdx.x;
    if (t >= EDGE_TOT) return;

    int s[EDGE_U], d[EDGE_U];
    if (g_is64) {
        const longlong2* e = (const longlong2*)e_raw;
        #pragma unroll
        for (int u = 0; u < EDGE_U; ++u) {
            longlong2 v = __ldg(&e[t + u * EDGE_TOT]);
            s[u] = (int)v.x; d[u] = (int)v.y;
        }
    } else {
        // int4 = (src0,dst0,src1,dst1): 2 edges per load
        const int4* e4 = (const int4*)e_raw;
        #pragma unroll
        for (int u = 0; u < EDGE_U / 2; ++u) {
            int4 v = __ldg(&e4[t + u * EDGE_TOT]);   // EDGE_TOT int4 stride covers 2*EDGE_TOT edges
            s[2*u]   = v.x; d[2*u]   = v.y;
            s[2*u+1] = v.z; d[2*u+1] = v.w;
        }
    }

    float a[EDGE_U], bb[EDGE_U];
    #pragma unroll
    for (int u = 0; u < EDGE_U; ++u) {
        a[u]  = __ldg(&g_alpha[s[u]]);
        bb[u] = __ldg(&g_beta[d[u]]);
    }

    float cc = g_cconst;
    #pragma unroll
    for (int u = 0; u < EDGE_U; ++u) {
        float sc = a[u] + bb[u] + cc;
        sc = (sc >= 0.f) ? sc : 0.2f * sc;
        atomicAdd(&g_n[d[u]], __expf(sc));
    }
}

// ---------------------------------------------------------------------------
// Output, FOUR nodes per warp (8 lanes per node, 4 float4 per lane):
// denom = (n==0)?1:n; y = relu(x/denom) + x; out = norm_w * y*inv_rms + norm_b
// ---------------------------------------------------------------------------
__global__ void k_out(const float* __restrict__ x,
                      const float* __restrict__ norm_w,
                      const float* __restrict__ norm_b,
                      float* __restrict__ out) {
    int gw   = (blockIdx.x * blockDim.x + threadIdx.x) >> 5;
    int lane = threadIdx.x & 31;
    int sub  = lane >> 3;
    int sl   = lane & 7;
    int node = gw * 4 + sub;
    if (node >= N_NODES) return;

    float n = __ldg(&g_n[node]);
    float inv = (n == 0.f) ? 1.f : __frcp_rn(n);

    const float4* xr = reinterpret_cast<const float4*>(x + (size_t)node * HID);
    float4 v0 = __ldg(&xr[sl]);
    float4 v1 = __ldg(&xr[sl + 8]);
    float4 v2 = __ldg(&xr[sl + 16]);
    float4 v3 = __ldg(&xr[sl + 24]);

    float4 y0, y1, y2, y3;
    y0.x = fmaxf(v0.x*inv, 0.f) + v0.x;  y0.y = fmaxf(v0.y*inv, 0.f) + v0.y;
    y0.z = fmaxf(v0.z*inv, 0.f) + v0.z;  y0.w = fmaxf(v0.w*inv, 0.f) + v0.w;
    y1.x = fmaxf(v1.x*inv, 0.f) + v1.x;  y1.y = fmaxf(v1.y*inv, 0.f) + v1.y;
    y1.z = fmaxf(v1.z*inv, 0.f) + v1.z;  y1.w = fmaxf(v1.w*inv, 0.f) + v1.w;
    y2.x = fmaxf(v2.x*inv, 0.f) + v2.x;  y2.y = fmaxf(v2.y*inv, 0.f) + v2.y;
    y2.z = fmaxf(v2.z*inv, 0.f) + v2.z;  y2.w = fmaxf(v2.w*inv, 0.f) + v2.w;
    y3.x = fmaxf(v3.x*inv, 0.f) + v3.x;  y3.y = fmaxf(v3.y*inv, 0.f) + v3.y;
    y3.z = fmaxf(v3.z*inv, 0.f) + v3.z;  y3.w = fmaxf(v3.w*inv, 0.f) + v3.w;

    float ss = y0.x*y0.x + y0.y*y0.y + y0.z*y0.z + y0.w*y0.w
             + y1.x*y1.x + y1.y*y1.y + y1.z*y1.z + y1.w*y1.w
             + y2.x*y2.x + y2.y*y2.y + y2.z*y2.z + y2.w*y2.w
             + y3.x*y3.x + y3.y*y3.y + y3.z*y3.z + y3.w*y3.w;
    #pragma unroll
    for (int o = 4; o > 0; o >>= 1)
        ss += __shfl_xor_sync(0xFFFFFFFFu, ss, o);

    float inv_rms = rsqrtf(ss * (1.f / (float)HID) + EPS);

    const float4* Wn = reinterpret_cast<const float4*>(norm_w);
    const float4* Bn = reinterpret_cast<const float4*>(norm_b);
    float4* orow = reinterpret_cast<float4*>(out + (size_t)node * HID);

    float4 w, bv, o4;
    w = __ldg(&Wn[sl]);      bv = __ldg(&Bn[sl]);
    o4.x = fmaf(w.x, y0.x*inv_rms, bv.x); o4.y = fmaf(w.y, y0.y*inv_rms, bv.y);
    o4.z = fmaf(w.z, y0.z*inv_rms, bv.z); o4.w = fmaf(w.w, y0.w*inv_rms, bv.w);
    __stcs(&orow[sl], o4);
    w = __ldg(&Wn[sl + 8]);  bv = __ldg(&Bn[sl + 8]);
    o4.x = fmaf(w.x, y1.x*inv_rms, bv.x); o4.y = fmaf(w.y, y1.y*inv_rms, bv.y);
    o4.z = fmaf(w.z, y1.z*inv_rms, bv.z); o4.w = fmaf(w.w, y1.w*inv_rms, bv.w);
    __stcs(&orow[sl + 8], o4);
    w = __ldg(&Wn[sl + 16]); bv = __ldg(&Bn[sl + 16]);
    o4.x = fmaf(w.x, y2.x*inv_rms, bv.x); o4.y = fmaf(w.y, y2.y*inv_rms, bv.y);
    o4.z = fmaf(w.z, y2.z*inv_rms, bv.z); o4.w = fmaf(w.w, y2.w*inv_rms, bv.w);
    __stcs(&orow[sl + 16], o4);
    w = __ldg(&Wn[sl + 24]); bv = __ldg(&Bn[sl + 24]);
    o4.x = fmaf(w.x, y3.x*inv_rms, bv.x); o4.y = fmaf(w.y, y3.y*inv_rms, bv.y);
    o4.z = fmaf(w.z, y3.z*inv_rms, bv.z); o4.w = fmaf(w.w, y3.w*inv_rms, bv.w);
    __stcs(&orow[sl + 24], o4);
}

// ---------------------------------------------------------------------------
extern "C" void kernel_launch(void* const* d_in, const int* in_sizes, int n_in,
                              void* d_out, int out_size) {
    const float* x      = (const float*)d_in[0];
    const float* W      = (const float*)d_in[1];
    const float* b      = (const float*)d_in[2];
    const float* att_w  = (const float*)d_in[3];
    const float* norm_w = (const float*)d_in[4];
    const float* norm_b = (const float*)d_in[5];
    const void*  e      = d_in[6];
    float* out          = (float*)d_out;

    (void)in_sizes; (void)n_in; (void)out_size;

    k_prep<<<1, 512>>>(W, b, att_w, (const long long*)e);

    {   // four nodes per warp
        int warps   = (N_NODES + 3) / 4;           // 25000
        int threads = 256;
        int blocks  = (warps * 32 + threads - 1) / threads;
        k_node<<<blocks, threads>>>(x);
    }
    {
        int threads = 256;
        int blocks  = (EDGE_TOT + threads - 1) / threads;
        k_edges<<<blocks, threads>>>(e);
    }
    {
        int warps   = (N_NODES + 3) / 4;
        int threads = 256;
        int blocks  = (warps * 32 + threads - 1) / threads;
        k_out<<<blocks, threads>>>(x, norm_w, norm_b, out);
    }
}